// round 15
// baseline (speedup 1.0000x reference)
#include <cuda_runtime.h>
#include <cuda_fp16.h>
#include <cstdint>

// Problem constants (fixed shapes)
#define BL_   2048           // B*L = 2*1024
#define L_    1024
#define D_    1024
#define ED_   2048
#define N_    16
#define R_    32
#define NPROJ 4096           // 2*ED
#define SPLITK 16

// ---------------- device scratch (static, no allocation) ----------------
__device__ float g_xs  [BL_ * ED_];
__device__ float g_z   [BL_ * ED_];
__device__ float g_xsc [BL_ * ED_];
__device__ float g_xdbl[BL_ * 64];
__device__ float g_xdbl_part[SPLITK][BL_ * 64];
__device__ float g_y   [BL_ * ED_];
__device__ float g_A   [ED_ * N_];

// ---------------- helpers ----------------
// split float4 (4 consecutive k) into packed half2 hi pair + lo pair
__device__ __forceinline__ void split4(float4 v, uint2& hi, uint2& lo) {
    __half2 h0 = __floats2half2_rn(v.x, v.y);
    __half2 h1 = __floats2half2_rn(v.z, v.w);
    float2 f0 = __half22float2(h0);
    float2 f1 = __half22float2(h1);
    __half2 l0 = __floats2half2_rn(v.x - f0.x, v.y - f0.y);
    __half2 l1 = __floats2half2_rn(v.z - f1.x, v.w - f1.y);
    hi.x = *reinterpret_cast<uint32_t*>(&h0);
    hi.y = *reinterpret_cast<uint32_t*>(&h1);
    lo.x = *reinterpret_cast<uint32_t*>(&l0);
    lo.y = *reinterpret_cast<uint32_t*>(&l1);
}
__device__ __forceinline__ void split4hi(float4 v, uint2& hi) {
    __half2 h0 = __floats2half2_rn(v.x, v.y);
    __half2 h1 = __floats2half2_rn(v.z, v.w);
    hi.x = *reinterpret_cast<uint32_t*>(&h0);
    hi.y = *reinterpret_cast<uint32_t*>(&h1);
}
__device__ __forceinline__ uint32_t smem_u32(const void* p) {
    uint32_t a;
    asm("{ .reg .u64 t; cvta.to.shared.u64 t, %1; cvt.u32.u64 %0, t; }" : "=r"(a) : "l"(p));
    return a;
}

#define MMA_F16(c, a0, a1, a2, a3, b0, b1) \
    asm volatile("mma.sync.aligned.m16n8k16.row.col.f32.f16.f16.f32 " \
        "{%0,%1,%2,%3}, {%4,%5,%6,%7}, {%8,%9}, {%0,%1,%2,%3};" \
        : "+f"((c)[0]), "+f"((c)[1]), "+f"((c)[2]), "+f"((c)[3]) \
        : "r"(a0), "r"(a1), "r"(a2), "r"(a3), "r"(b0), "r"(b1))

#define LDSM4(r0, r1, r2, r3, addr) \
    asm volatile("ldmatrix.sync.aligned.m8n8.x4.shared.b16 {%0,%1,%2,%3}, [%4];" \
        : "=r"(r0), "=r"(r1), "=r"(r2), "=r"(r3) : "r"(addr))

// ============================================================
// 2-term FP16 split GEMM: D += Ahi*Bhi + Alo*Bhi
// hi/lo split ONCE at STS time (fp32 LDG prefetch keeps overlap).
// Fragment loads via ldmatrix.x4 (16 LDSM vs 64 LDS.32 per chunk/warp).
// CTA 64x128, BK=32, 128 threads = 4 warps (2m x 2n), warp 32x64.
// SMEM fp16: Ahi/Alo 64x40h, Bhi 128x40h (PADH=40 -> LDSM conflict-free).
// 3 CTAs/SM (12 warps) now that LDSM relieved issue pressure.
// EPI 0: C[m*Nout+n]; EPI 1: split to g_xs / g_z.
// ============================================================
#define PADH 40                          // halves per row (80 B)
#define AHI_OFF 0
#define ALO_OFF 5120                     // 64*80
#define BHI_OFF 10240
#define STAGE_B 20480                    // bytes per stage

template<int EPI>
__global__ void __launch_bounds__(128, 3)
gemm_mma(const float* __restrict__ A, const float* __restrict__ B,
         float* __restrict__ C, int Nout, int K)
{
    extern __shared__ char smem[];
    const int tid  = threadIdx.x;
    const int wid  = tid >> 5;           // 0..3
    const int lane = tid & 31;
    const int gq   = lane >> 2;          // 0..7
    const int tig  = lane & 3;           // 0..3
    const int m0   = blockIdx.y * 64;
    const int n0   = blockIdx.x * 128;
    const int wm   = (wid >> 1) * 32;    // warp m offset (0/32)
    const int wn   = (wid & 1) * 64;     // warp n offset (0/64)
    const int NC   = K >> 5;

    float acc[2][8][4];
#pragma unroll
    for (int i = 0; i < 2; i++)
#pragma unroll
        for (int j = 0; j < 8; j++)
#pragma unroll
            for (int q = 0; q < 4; q++) acc[i][j][q] = 0.f;

    const uint32_t sbase = smem_u32(smem);

    // ldmatrix per-lane address components (bytes, relative to stage base)
    const uint32_t aRowOff = (uint32_t)(wm + (lane & 15)) * 80u + (uint32_t)(lane >> 4) * 16u;
    const uint32_t bRowOff = (uint32_t)(wn + 8 * ((lane >> 4) & 1) + (lane & 7)) * 80u
                           + (uint32_t)((lane >> 3) & 1) * 16u;

    // loader mapping: 16 rows x 8 col-quads
    const int lr  = tid >> 3;            // 0..15
    const int lc4 = (tid & 7) << 2;      // 0,4,...,28
    const float* ga = A + (size_t)(m0 + lr) * K + lc4;
    const float* gb = B + (size_t)(n0 + lr) * K + lc4;
    const uint32_t sO = (uint32_t)(lr * PADH + lc4) * 2;

    float4 pfA[4], pfB[8];

    auto ldg_chunk = [&](int c) {
        const float* pa = ga + c * 32;
        const float* pb = gb + c * 32;
#pragma unroll
        for (int i = 0; i < 4; i++) pfA[i] = *(const float4*)(pa + (size_t)(i * 16) * K);
#pragma unroll
        for (int i = 0; i < 8; i++) pfB[i] = *(const float4*)(pb + (size_t)(i * 16) * K);
    };
    auto sts_chunk = [&](int buf) {
        char* st = smem + buf * STAGE_B;
#pragma unroll
        for (int i = 0; i < 4; i++) {
            uint2 hi, lo; split4(pfA[i], hi, lo);
            uint32_t o = sO + (uint32_t)(i * 16 * PADH) * 2;
            *(uint2*)(st + AHI_OFF + o) = hi;
            *(uint2*)(st + ALO_OFF + o) = lo;
        }
#pragma unroll
        for (int i = 0; i < 8; i++) {
            uint2 hi; split4hi(pfB[i], hi);
            uint32_t o = sO + (uint32_t)(i * 16 * PADH) * 2;
            *(uint2*)(st + BHI_OFF + o) = hi;
        }
    };

    // ---- prologue ----
    ldg_chunk(0);
    sts_chunk(0);
    if (NC > 1) ldg_chunk(1);
    __syncthreads();

    for (int c = 0; c < NC; c++) {
        const int buf = c & 1;
        if (c + 1 < NC) sts_chunk((c + 1) & 1);
        if (c + 2 < NC) ldg_chunk(c + 2);

        const uint32_t st = sbase + buf * STAGE_B;

#pragma unroll
        for (int ks = 0; ks < 2; ks++) {
            uint32_t bh[8][2];
#pragma unroll
            for (int t = 0; t < 4; t++) {
                uint32_t addr = st + BHI_OFF + bRowOff + (uint32_t)(t * 1280 + ks * 32);
                LDSM4(bh[2 * t][0], bh[2 * t][1], bh[2 * t + 1][0], bh[2 * t + 1][1], addr);
            }
#pragma unroll
            for (int mt = 0; mt < 2; mt++) {
                uint32_t aaddr = st + AHI_OFF + aRowOff + (uint32_t)(mt * 1280 + ks * 32);
                uint32_t ah[4], al[4];
                LDSM4(ah[0], ah[1], ah[2], ah[3], aaddr);
                LDSM4(al[0], al[1], al[2], al[3], aaddr + (ALO_OFF - AHI_OFF));
#pragma unroll
                for (int nt = 0; nt < 8; nt++) {
                    MMA_F16(acc[mt][nt], ah[0], ah[1], ah[2], ah[3], bh[nt][0], bh[nt][1]);
                    MMA_F16(acc[mt][nt], al[0], al[1], al[2], al[3], bh[nt][0], bh[nt][1]);
                }
            }
        }
        __syncthreads();
    }

    // ---- epilogue ----
    float* dst;
    int ld, ncol0;
    if (EPI == 1) {
        if (n0 < ED_) { dst = g_xs; ncol0 = n0; }
        else          { dst = g_z;  ncol0 = n0 - ED_; }
        ld = ED_;
    } else {
        dst = C; ncol0 = n0; ld = Nout;
    }
#pragma unroll
    for (int mt = 0; mt < 2; mt++) {
        const int m = m0 + wm + 16 * mt + gq;
#pragma unroll
        for (int nt = 0; nt < 8; nt++) {
            const int n = ncol0 + wn + 8 * nt + 2 * tig;
            float2 v0 = make_float2(acc[mt][nt][0], acc[mt][nt][1]);
            float2 v1 = make_float2(acc[mt][nt][2], acc[mt][nt][3]);
            *(float2*)(dst + (size_t)m * ld + n)       = v0;
            *(float2*)(dst + (size_t)(m + 8) * ld + n) = v1;
        }
    }
}

// ---------------- tiny precompute: A = -exp(A_log) ----------------
__global__ void prep_A_kernel(const float* __restrict__ A_log) {
    int i = blockIdx.x * blockDim.x + threadIdx.x;
    if (i < ED_ * N_) g_A[i] = -expf(A_log[i]);
}

// ---------------- fused conv+silu + split-K x_proj GEMM ----------------
__global__ void __launch_bounds__(256)
gemm_xproj_fused(const float* __restrict__ B,     // x_proj_w (64,2048)
                 const float* __restrict__ cw,    // conv_w (2048*3)
                 const float* __restrict__ cb,    // conv_b
                 int K)
{
    constexpr int BM = 64, BN = 64, BK = 16, TM = 4, TN = 4;
    __shared__ float As[BK * BM];
    __shared__ float Bs[BK * BN];

    const int t  = threadIdx.x;
    const int m0 = blockIdx.y * BM;
    const int z  = blockIdx.z;
    const int KS = K / SPLITK;
    const int kbeg = z * KS;
    const int tr = t / (BN / TN);
    const int tc = t % (BN / TN);

    float acc[TM][TN];
#pragma unroll
    for (int i = 0; i < TM; i++)
#pragma unroll
        for (int j = 0; j < TN; j++) acc[i][j] = 0.f;

    const int row = t >> 2;          // 0..63
    const int cc  = t & 3;           // 0..3
    const int m   = m0 + row;
    const int l   = m & (L_ - 1);

    for (int k0 = kbeg; k0 < kbeg + KS; k0 += BK) {
        {
            const int e = k0 + cc * 4;
            float4 cur  = *(const float4*)(g_xs + (size_t)m * ED_ + e);
            float4 prev = (l > 0)      ? *(const float4*)(g_xs + (size_t)(m - 1) * ED_ + e)
                                       : make_float4(0.f, 0.f, 0.f, 0.f);
            float4 nxt  = (l < L_ - 1) ? *(const float4*)(g_xs + (size_t)(m + 1) * ED_ + e)
                                       : make_float4(0.f, 0.f, 0.f, 0.f);
            float4 w0 = *(const float4*)(cw + (size_t)e * 3);
            float4 w1 = *(const float4*)(cw + (size_t)e * 3 + 4);
            float4 w2 = *(const float4*)(cw + (size_t)e * 3 + 8);
            float4 bb = *(const float4*)(cb + e);

            float r0 = fmaf(prev.x, w0.x, fmaf(cur.x, w0.y, fmaf(nxt.x, w0.z, bb.x)));
            float r1 = fmaf(prev.y, w0.w, fmaf(cur.y, w1.x, fmaf(nxt.y, w1.y, bb.y)));
            float r2 = fmaf(prev.z, w1.z, fmaf(cur.z, w1.w, fmaf(nxt.z, w2.x, bb.z)));
            float r3 = fmaf(prev.w, w2.y, fmaf(cur.w, w2.z, fmaf(nxt.w, w2.w, bb.w)));

            float4 o;
            o.x = r0 * (1.f / (1.f + __expf(-r0)));
            o.y = r1 * (1.f / (1.f + __expf(-r1)));
            o.z = r2 * (1.f / (1.f + __expf(-r2)));
            o.w = r3 * (1.f / (1.f + __expf(-r3)));
            *(float4*)(g_xsc + (size_t)m * ED_ + e) = o;

            As[(cc * 4 + 0) * BM + row] = o.x;
            As[(cc * 4 + 1) * BM + row] = o.y;
            As[(cc * 4 + 2) * BM + row] = o.z;
            As[(cc * 4 + 3) * BM + row] = o.w;

            float4 w = *(const float4*)(B + (size_t)row * K + k0 + cc * 4);
            Bs[(cc * 4 + 0) * BN + row] = w.x;
            Bs[(cc * 4 + 1) * BN + row] = w.y;
            Bs[(cc * 4 + 2) * BN + row] = w.z;
            Bs[(cc * 4 + 3) * BN + row] = w.w;
        }
        __syncthreads();
#pragma unroll
        for (int kk = 0; kk < BK; kk++) {
            float af[TM], bf[TN];
#pragma unroll
            for (int i = 0; i < TM; i++) af[i] = As[kk * BM + tr * TM + i];
#pragma unroll
            for (int j = 0; j < TN; j++) bf[j] = Bs[kk * BN + tc * TN + j];
#pragma unroll
            for (int i = 0; i < TM; i++)
#pragma unroll
                for (int j = 0; j < TN; j++)
                    acc[i][j] = fmaf(af[i], bf[j], acc[i][j]);
        }
        __syncthreads();
    }
#pragma unroll
    for (int i = 0; i < TM; i++) {
        int mm = m0 + tr * TM + i;
#pragma unroll
        for (int j = 0; j < TN; j++) {
            int n = tc * TN + j;
            g_xdbl_part[z][(size_t)mm * 64 + n] = acc[i][j];
        }
    }
}

__global__ void reduce_xdbl_kernel() {
    int i = blockIdx.x * blockDim.x + threadIdx.x;
    if (i >= BL_ * 64 / 4) return;
    float4 s = make_float4(0.f, 0.f, 0.f, 0.f);
#pragma unroll
    for (int z = 0; z < SPLITK; z++) {
        float4 v = *((const float4*)g_xdbl_part[z] + i);
        s.x += v.x; s.y += v.y; s.z += v.z; s.w += v.w;
    }
    *((float4*)g_xdbl + i) = s;
}

// ---------------- fused delta + SSM step ----------------
__global__ void __launch_bounds__(256)
ssm_fused(const float* __restrict__ h,
          const float* __restrict__ W,      // dt_proj_w (2048,32)
          const float* __restrict__ bias,   // dt_proj_b
          const float* __restrict__ Dvec,
          float* __restrict__ hout)
{
    const int tid = threadIdx.x;
    const int s   = blockIdx.x & 7;
    const int mg  = blockIdx.x >> 3;
    const int e   = (s << 8) + tid;

    __shared__ float sx[8][64];
    {
        int idx = tid * 2;
        float2 v = *(const float2*)(g_xdbl + (size_t)(mg * 8 + (idx >> 6)) * 64 + (idx & 63));
        sx[idx >> 6][idx & 63]       = v.x;
        sx[idx >> 6][(idx & 63) + 1] = v.y;
    }
    __syncthreads();

    float wr[32];
#pragma unroll
    for (int q = 0; q < 8; q++) {
        float4 v = *(const float4*)(W + (size_t)e * 32 + q * 4);
        wr[q * 4 + 0] = v.x; wr[q * 4 + 1] = v.y; wr[q * 4 + 2] = v.z; wr[q * 4 + 3] = v.w;
    }
    const float bv   = bias[e];
    const float dval = Dvec[e];
    float4 a4[4];
#pragma unroll
    for (int q = 0; q < 4; q++) a4[q] = ((const float4*)(g_A + (size_t)e * N_))[q];

#pragma unroll
    for (int mm = 0; mm < 8; mm++) {
        const int m = mg * 8 + mm;
        float acc = bv;
#pragma unroll
        for (int r = 0; r < 32; r++) acc = fmaf(sx[mm][r], wr[r], acc);
        const float delta = (acc > 20.f) ? acc : log1pf(__expf(acc));

        const size_t me = (size_t)m * ED_ + e;
        const float xs = g_xsc[me];
        const float z  = g_z[me];
        const float dx = delta * xs;

        const float4* h4 = (const float4*)(h + me * N_);
        float4*       o4 = (float4*)(hout + me * N_);

        float y = 0.f;
#pragma unroll
        for (int q = 0; q < 4; q++) {
            float4 hv = h4[q];
            float4 av = a4[q];
            float4 o;
            o.x = fmaf(__expf(delta * av.x), hv.x, dx * sx[mm][32 + q * 4 + 0]);
            o.y = fmaf(__expf(delta * av.y), hv.y, dx * sx[mm][32 + q * 4 + 1]);
            o.z = fmaf(__expf(delta * av.z), hv.z, dx * sx[mm][32 + q * 4 + 2]);
            o.w = fmaf(__expf(delta * av.w), hv.w, dx * sx[mm][32 + q * 4 + 3]);
            o4[q] = o;
            y = fmaf(o.x, sx[mm][48 + q * 4 + 0], y);
            y = fmaf(o.y, sx[mm][48 + q * 4 + 1], y);
            y = fmaf(o.z, sx[mm][48 + q * 4 + 2], y);
            y = fmaf(o.w, sx[mm][48 + q * 4 + 3], y);
        }
        y = fmaf(dval, xs, y);
        const float sz = z * (1.f / (1.f + __expf(-z)));
        g_y[me] = y * sz;
    }
}

// ---------------- launch ----------------
extern "C" void kernel_launch(void* const* d_in, const int* in_sizes, int n_in,
                              void* d_out, int out_size)
{
    const float* x          = (const float*)d_in[0];
    const float* h          = (const float*)d_in[1];
    const float* in_proj_w  = (const float*)d_in[2];
    const float* conv_w     = (const float*)d_in[3];
    const float* conv_b     = (const float*)d_in[4];
    const float* x_proj_w   = (const float*)d_in[5];
    const float* dt_proj_w  = (const float*)d_in[6];
    const float* dt_proj_b  = (const float*)d_in[7];
    const float* A_log      = (const float*)d_in[8];
    const float* Dvec       = (const float*)d_in[9];
    const float* out_proj_w = (const float*)d_in[10];

    float* out  = (float*)d_out;
    float* hout = out + (size_t)BL_ * D_;

    float* p_y = nullptr;
    cudaGetSymbolAddress((void**)&p_y, g_y);

    const int SMEM_GEMM = 2 * STAGE_B;   // 40960 bytes
    cudaFuncSetAttribute(gemm_mma<1>, cudaFuncAttributeMaxDynamicSharedMemorySize, SMEM_GEMM);
    cudaFuncSetAttribute(gemm_mma<0>, cudaFuncAttributeMaxDynamicSharedMemorySize, SMEM_GEMM);

    // 1. A = -exp(A_log)
    prep_A_kernel<<<(ED_ * N_ + 255) / 256, 256>>>(A_log);

    // 2. in_proj GEMM (2-term fp16 split, ldmatrix, 3 CTAs/SM): split xs / z
    gemm_mma<1><<<dim3(NPROJ / 128, BL_ / 64), 128, SMEM_GEMM>>>(
        x, in_proj_w, nullptr, NPROJ, D_);

    // 3. x_proj GEMM with fused conv+silu (writes g_xsc), split-K + reduce
    gemm_xproj_fused<<<dim3(1, BL_ / 64, SPLITK), 256>>>(x_proj_w, conv_w, conv_b, ED_);
    reduce_xdbl_kernel<<<(BL_ * 64 / 4 + 255) / 256, 256>>>();

    // 4. fused delta + SSM (writes h_new to output + y*silu(z) scratch)
    ssm_fused<<<(BL_ / 8) * 8, 256>>>(h, dt_proj_w, dt_proj_b, Dvec, hout);

    // 5. out_proj GEMM (2-term fp16 split, ldmatrix, 3 CTAs/SM)
    gemm_mma<0><<<dim3(D_ / 128, BL_ / 64), 128, SMEM_GEMM>>>(
        p_y, out_proj_w, out, D_, ED_);
}

// round 16
// speedup vs baseline: 1.0177x; 1.0177x over previous
#include <cuda_runtime.h>
#include <cuda_fp16.h>
#include <cstdint>

// Problem constants (fixed shapes)
#define BL_   2048           // B*L = 2*1024
#define L_    1024
#define D_    1024
#define ED_   2048
#define N_    16
#define R_    32
#define NPROJ 4096           // 2*ED
#define SPLITK 16

// ---------------- device scratch (static, no allocation) ----------------
__device__ float g_xs  [BL_ * ED_];
__device__ float g_z   [BL_ * ED_];
__device__ float g_xsc [BL_ * ED_];
__device__ float g_xdbl_part[SPLITK][BL_ * 64];
__device__ float g_y   [BL_ * ED_];

// ---------------- helpers ----------------
// split float4 (4 consecutive k) into packed half2 hi pair + lo pair
__device__ __forceinline__ void split4(float4 v, uint2& hi, uint2& lo) {
    __half2 h0 = __floats2half2_rn(v.x, v.y);
    __half2 h1 = __floats2half2_rn(v.z, v.w);
    float2 f0 = __half22float2(h0);
    float2 f1 = __half22float2(h1);
    __half2 l0 = __floats2half2_rn(v.x - f0.x, v.y - f0.y);
    __half2 l1 = __floats2half2_rn(v.z - f1.x, v.w - f1.y);
    hi.x = *reinterpret_cast<uint32_t*>(&h0);
    hi.y = *reinterpret_cast<uint32_t*>(&h1);
    lo.x = *reinterpret_cast<uint32_t*>(&l0);
    lo.y = *reinterpret_cast<uint32_t*>(&l1);
}
__device__ __forceinline__ void split4hi(float4 v, uint2& hi) {
    __half2 h0 = __floats2half2_rn(v.x, v.y);
    __half2 h1 = __floats2half2_rn(v.z, v.w);
    hi.x = *reinterpret_cast<uint32_t*>(&h0);
    hi.y = *reinterpret_cast<uint32_t*>(&h1);
}
__device__ __forceinline__ uint32_t smem_u32(const void* p) {
    uint32_t a;
    asm("{ .reg .u64 t; cvta.to.shared.u64 t, %1; cvt.u32.u64 %0, t; }" : "=r"(a) : "l"(p));
    return a;
}

#define MMA_F16(c, a0, a1, a2, a3, b0, b1) \
    asm volatile("mma.sync.aligned.m16n8k16.row.col.f32.f16.f16.f32 " \
        "{%0,%1,%2,%3}, {%4,%5,%6,%7}, {%8,%9}, {%0,%1,%2,%3};" \
        : "+f"((c)[0]), "+f"((c)[1]), "+f"((c)[2]), "+f"((c)[3]) \
        : "r"(a0), "r"(a1), "r"(a2), "r"(a3), "r"(b0), "r"(b1))

#define LDSM4(r0, r1, r2, r3, addr) \
    asm volatile("ldmatrix.sync.aligned.m8n8.x4.shared.b16 {%0,%1,%2,%3}, [%4];" \
        : "=r"(r0), "=r"(r1), "=r"(r2), "=r"(r3) : "r"(addr))

// ============================================================
// 2-term FP16 split GEMM: D += Ahi*Bhi + Alo*Bhi
// hi/lo split ONCE at STS time (fp32 LDG prefetch keeps overlap).
// Fragment loads via ldmatrix.x4. CTA 64x128, BK=32, 128 threads =
// 4 warps (2m x 2n), warp 32x64. PADH=40 -> conflict-free. 2 CTAs/SM.
// EPI 0: C[m*Nout+n]; EPI 1: split to g_xs / g_z.
// ============================================================
#define PADH 40                          // halves per row (80 B)
#define AHI_OFF 0
#define ALO_OFF 5120                     // 64*80
#define BHI_OFF 10240
#define STAGE_B 20480                    // bytes per stage

template<int EPI>
__global__ void __launch_bounds__(128, 2)
gemm_mma(const float* __restrict__ A, const float* __restrict__ B,
         float* __restrict__ C, int Nout, int K)
{
    extern __shared__ char smem[];
    const int tid  = threadIdx.x;
    const int wid  = tid >> 5;           // 0..3
    const int lane = tid & 31;
    const int gq   = lane >> 2;          // 0..7
    const int tig  = lane & 3;           // 0..3
    const int m0   = blockIdx.y * 64;
    const int n0   = blockIdx.x * 128;
    const int wm   = (wid >> 1) * 32;    // warp m offset (0/32)
    const int wn   = (wid & 1) * 64;     // warp n offset (0/64)
    const int NC   = K >> 5;

    float acc[2][8][4];
#pragma unroll
    for (int i = 0; i < 2; i++)
#pragma unroll
        for (int j = 0; j < 8; j++)
#pragma unroll
            for (int q = 0; q < 4; q++) acc[i][j][q] = 0.f;

    const uint32_t sbase = smem_u32(smem);

    // ldmatrix per-lane address components (bytes, relative to stage base)
    const uint32_t aRowOff = (uint32_t)(wm + (lane & 15)) * 80u + (uint32_t)(lane >> 4) * 16u;
    const uint32_t bRowOff = (uint32_t)(wn + 8 * ((lane >> 4) & 1) + (lane & 7)) * 80u
                           + (uint32_t)((lane >> 3) & 1) * 16u;

    // loader mapping: 16 rows x 8 col-quads
    const int lr  = tid >> 3;            // 0..15
    const int lc4 = (tid & 7) << 2;      // 0,4,...,28
    const float* ga = A + (size_t)(m0 + lr) * K + lc4;
    const float* gb = B + (size_t)(n0 + lr) * K + lc4;
    const uint32_t sO = (uint32_t)(lr * PADH + lc4) * 2;

    float4 pfA[4], pfB[8];

    auto ldg_chunk = [&](int c) {
        const float* pa = ga + c * 32;
        const float* pb = gb + c * 32;
#pragma unroll
        for (int i = 0; i < 4; i++) pfA[i] = *(const float4*)(pa + (size_t)(i * 16) * K);
#pragma unroll
        for (int i = 0; i < 8; i++) pfB[i] = *(const float4*)(pb + (size_t)(i * 16) * K);
    };
    auto sts_chunk = [&](int buf) {
        char* st = smem + buf * STAGE_B;
#pragma unroll
        for (int i = 0; i < 4; i++) {
            uint2 hi, lo; split4(pfA[i], hi, lo);
            uint32_t o = sO + (uint32_t)(i * 16 * PADH) * 2;
            *(uint2*)(st + AHI_OFF + o) = hi;
            *(uint2*)(st + ALO_OFF + o) = lo;
        }
#pragma unroll
        for (int i = 0; i < 8; i++) {
            uint2 hi; split4hi(pfB[i], hi);
            uint32_t o = sO + (uint32_t)(i * 16 * PADH) * 2;
            *(uint2*)(st + BHI_OFF + o) = hi;
        }
    };

    // ---- prologue ----
    ldg_chunk(0);
    sts_chunk(0);
    if (NC > 1) ldg_chunk(1);
    __syncthreads();

    for (int c = 0; c < NC; c++) {
        const int buf = c & 1;
        if (c + 1 < NC) sts_chunk((c + 1) & 1);
        if (c + 2 < NC) ldg_chunk(c + 2);

        const uint32_t st = sbase + buf * STAGE_B;

#pragma unroll
        for (int ks = 0; ks < 2; ks++) {
            uint32_t bh[8][2];
#pragma unroll
            for (int t = 0; t < 4; t++) {
                uint32_t addr = st + BHI_OFF + bRowOff + (uint32_t)(t * 1280 + ks * 32);
                LDSM4(bh[2 * t][0], bh[2 * t][1], bh[2 * t + 1][0], bh[2 * t + 1][1], addr);
            }
#pragma unroll
            for (int mt = 0; mt < 2; mt++) {
                uint32_t aaddr = st + AHI_OFF + aRowOff + (uint32_t)(mt * 1280 + ks * 32);
                uint32_t ah[4], al[4];
                LDSM4(ah[0], ah[1], ah[2], ah[3], aaddr);
                LDSM4(al[0], al[1], al[2], al[3], aaddr + (ALO_OFF - AHI_OFF));
#pragma unroll
                for (int nt = 0; nt < 8; nt++) {
                    MMA_F16(acc[mt][nt], ah[0], ah[1], ah[2], ah[3], bh[nt][0], bh[nt][1]);
                    MMA_F16(acc[mt][nt], al[0], al[1], al[2], al[3], bh[nt][0], bh[nt][1]);
                }
            }
        }
        __syncthreads();
    }

    // ---- epilogue ----
    float* dst;
    int ld, ncol0;
    if (EPI == 1) {
        if (n0 < ED_) { dst = g_xs; ncol0 = n0; }
        else          { dst = g_z;  ncol0 = n0 - ED_; }
        ld = ED_;
    } else {
        dst = C; ncol0 = n0; ld = Nout;
    }
#pragma unroll
    for (int mt = 0; mt < 2; mt++) {
        const int m = m0 + wm + 16 * mt + gq;
#pragma unroll
        for (int nt = 0; nt < 8; nt++) {
            const int n = ncol0 + wn + 8 * nt + 2 * tig;
            float2 v0 = make_float2(acc[mt][nt][0], acc[mt][nt][1]);
            float2 v1 = make_float2(acc[mt][nt][2], acc[mt][nt][3]);
            *(float2*)(dst + (size_t)m * ld + n)       = v0;
            *(float2*)(dst + (size_t)(m + 8) * ld + n) = v1;
        }
    }
}

// ---------------- fused conv+silu + split-K x_proj GEMM ----------------
__global__ void __launch_bounds__(256)
gemm_xproj_fused(const float* __restrict__ B,     // x_proj_w (64,2048)
                 const float* __restrict__ cw,    // conv_w (2048*3)
                 const float* __restrict__ cb,    // conv_b
                 int K)
{
    constexpr int BM = 64, BN = 64, BK = 16, TM = 4, TN = 4;
    __shared__ float As[BK * BM];
    __shared__ float Bs[BK * BN];

    const int t  = threadIdx.x;
    const int m0 = blockIdx.y * BM;
    const int z  = blockIdx.z;
    const int KS = K / SPLITK;
    const int kbeg = z * KS;
    const int tr = t / (BN / TN);
    const int tc = t % (BN / TN);

    float acc[TM][TN];
#pragma unroll
    for (int i = 0; i < TM; i++)
#pragma unroll
        for (int j = 0; j < TN; j++) acc[i][j] = 0.f;

    const int row = t >> 2;          // 0..63
    const int cc  = t & 3;           // 0..3
    const int m   = m0 + row;
    const int l   = m & (L_ - 1);

    for (int k0 = kbeg; k0 < kbeg + KS; k0 += BK) {
        {
            const int e = k0 + cc * 4;
            float4 cur  = *(const float4*)(g_xs + (size_t)m * ED_ + e);
            float4 prev = (l > 0)      ? *(const float4*)(g_xs + (size_t)(m - 1) * ED_ + e)
                                       : make_float4(0.f, 0.f, 0.f, 0.f);
            float4 nxt  = (l < L_ - 1) ? *(const float4*)(g_xs + (size_t)(m + 1) * ED_ + e)
                                       : make_float4(0.f, 0.f, 0.f, 0.f);
            float4 w0 = *(const float4*)(cw + (size_t)e * 3);
            float4 w1 = *(const float4*)(cw + (size_t)e * 3 + 4);
            float4 w2 = *(const float4*)(cw + (size_t)e * 3 + 8);
            float4 bb = *(const float4*)(cb + e);

            float r0 = fmaf(prev.x, w0.x, fmaf(cur.x, w0.y, fmaf(nxt.x, w0.z, bb.x)));
            float r1 = fmaf(prev.y, w0.w, fmaf(cur.y, w1.x, fmaf(nxt.y, w1.y, bb.y)));
            float r2 = fmaf(prev.z, w1.z, fmaf(cur.z, w1.w, fmaf(nxt.z, w2.x, bb.z)));
            float r3 = fmaf(prev.w, w2.y, fmaf(cur.w, w2.z, fmaf(nxt.w, w2.w, bb.w)));

            float4 o;
            o.x = r0 * (1.f / (1.f + __expf(-r0)));
            o.y = r1 * (1.f / (1.f + __expf(-r1)));
            o.z = r2 * (1.f / (1.f + __expf(-r2)));
            o.w = r3 * (1.f / (1.f + __expf(-r3)));
            *(float4*)(g_xsc + (size_t)m * ED_ + e) = o;

            As[(cc * 4 + 0) * BM + row] = o.x;
            As[(cc * 4 + 1) * BM + row] = o.y;
            As[(cc * 4 + 2) * BM + row] = o.z;
            As[(cc * 4 + 3) * BM + row] = o.w;

            float4 w = *(const float4*)(B + (size_t)row * K + k0 + cc * 4);
            Bs[(cc * 4 + 0) * BN + row] = w.x;
            Bs[(cc * 4 + 1) * BN + row] = w.y;
            Bs[(cc * 4 + 2) * BN + row] = w.z;
            Bs[(cc * 4 + 3) * BN + row] = w.w;
        }
        __syncthreads();
#pragma unroll
        for (int kk = 0; kk < BK; kk++) {
            float af[TM], bf[TN];
#pragma unroll
            for (int i = 0; i < TM; i++) af[i] = As[kk * BM + tr * TM + i];
#pragma unroll
            for (int j = 0; j < TN; j++) bf[j] = Bs[kk * BN + tc * TN + j];
#pragma unroll
            for (int i = 0; i < TM; i++)
#pragma unroll
                for (int j = 0; j < TN; j++)
                    acc[i][j] = fmaf(af[i], bf[j], acc[i][j]);
        }
        __syncthreads();
    }
#pragma unroll
    for (int i = 0; i < TM; i++) {
        int mm = m0 + tr * TM + i;
#pragma unroll
        for (int j = 0; j < TN; j++) {
            int n = tc * TN + j;
            g_xdbl_part[z][(size_t)mm * 64 + n] = acc[i][j];
        }
    }
}

// ---------------- fused reduce + prep_A + delta + SSM step ----------------
// Block: 256 threads, 8 tokens x 256 channels. Reduces the SPLITK xdbl
// partials for its 8 tokens into SMEM (same z-order as the old reduce
// kernel -> bit-identical), computes -exp(A_log) inline (reused over 8
// tokens), then delta/softplus + SSM. Normal loads/stores (no streaming
// hints -- those regressed in R10).
__global__ void __launch_bounds__(256)
ssm_fused(const float* __restrict__ h,
          const float* __restrict__ W,      // dt_proj_w (2048,32)
          const float* __restrict__ bias,   // dt_proj_b
          const float* __restrict__ Dvec,
          const float* __restrict__ A_log,  // (2048,16)
          float* __restrict__ hout)
{
    const int tid = threadIdx.x;
    const int s   = blockIdx.x & 7;
    const int mg  = blockIdx.x >> 3;
    const int e   = (s << 8) + tid;

    __shared__ float sx[8][64];
    {
        const int idx = tid * 2;
        const int row = idx >> 6;          // 0..7
        const int col = idx & 63;
        const size_t off = (size_t)(mg * 8 + row) * 64 + col;
        float2 acc2 = make_float2(0.f, 0.f);
#pragma unroll
        for (int zz = 0; zz < SPLITK; zz++) {
            float2 v = *(const float2*)(g_xdbl_part[zz] + off);
            acc2.x += v.x; acc2.y += v.y;
        }
        sx[row][col]     = acc2.x;
        sx[row][col + 1] = acc2.y;
    }

    float wr[32];
#pragma unroll
    for (int q = 0; q < 8; q++) {
        float4 v = *(const float4*)(W + (size_t)e * 32 + q * 4);
        wr[q * 4 + 0] = v.x; wr[q * 4 + 1] = v.y; wr[q * 4 + 2] = v.z; wr[q * 4 + 3] = v.w;
    }
    const float bv   = bias[e];
    const float dval = Dvec[e];
    float4 a4[4];
#pragma unroll
    for (int q = 0; q < 4; q++) {
        float4 v = ((const float4*)(A_log + (size_t)e * N_))[q];
        a4[q].x = -__expf(v.x);
        a4[q].y = -__expf(v.y);
        a4[q].z = -__expf(v.z);
        a4[q].w = -__expf(v.w);
    }
    __syncthreads();

#pragma unroll
    for (int mm = 0; mm < 8; mm++) {
        const int m = mg * 8 + mm;
        float acc = bv;
#pragma unroll
        for (int r = 0; r < 32; r++) acc = fmaf(sx[mm][r], wr[r], acc);
        const float delta = (acc > 20.f) ? acc : log1pf(__expf(acc));

        const size_t me = (size_t)m * ED_ + e;
        const float xs = g_xsc[me];
        const float z  = g_z[me];
        const float dx = delta * xs;

        const float4* h4 = (const float4*)(h + me * N_);
        float4*       o4 = (float4*)(hout + me * N_);

        float y = 0.f;
#pragma unroll
        for (int q = 0; q < 4; q++) {
            float4 hv = h4[q];
            float4 av = a4[q];
            float4 o;
            o.x = fmaf(__expf(delta * av.x), hv.x, dx * sx[mm][32 + q * 4 + 0]);
            o.y = fmaf(__expf(delta * av.y), hv.y, dx * sx[mm][32 + q * 4 + 1]);
            o.z = fmaf(__expf(delta * av.z), hv.z, dx * sx[mm][32 + q * 4 + 2]);
            o.w = fmaf(__expf(delta * av.w), hv.w, dx * sx[mm][32 + q * 4 + 3]);
            o4[q] = o;
            y = fmaf(o.x, sx[mm][48 + q * 4 + 0], y);
            y = fmaf(o.y, sx[mm][48 + q * 4 + 1], y);
            y = fmaf(o.z, sx[mm][48 + q * 4 + 2], y);
            y = fmaf(o.w, sx[mm][48 + q * 4 + 3], y);
        }
        y = fmaf(dval, xs, y);
        const float sz = z * (1.f / (1.f + __expf(-z)));
        g_y[me] = y * sz;
    }
}

// ---------------- launch ----------------
extern "C" void kernel_launch(void* const* d_in, const int* in_sizes, int n_in,
                              void* d_out, int out_size)
{
    const float* x          = (const float*)d_in[0];
    const float* h          = (const float*)d_in[1];
    const float* in_proj_w  = (const float*)d_in[2];
    const float* conv_w     = (const float*)d_in[3];
    const float* conv_b     = (const float*)d_in[4];
    const float* x_proj_w   = (const float*)d_in[5];
    const float* dt_proj_w  = (const float*)d_in[6];
    const float* dt_proj_b  = (const float*)d_in[7];
    const float* A_log      = (const float*)d_in[8];
    const float* Dvec       = (const float*)d_in[9];
    const float* out_proj_w = (const float*)d_in[10];

    float* out  = (float*)d_out;
    float* hout = out + (size_t)BL_ * D_;

    float* p_y = nullptr;
    cudaGetSymbolAddress((void**)&p_y, g_y);

    const int SMEM_GEMM = 2 * STAGE_B;   // 40960 bytes
    cudaFuncSetAttribute(gemm_mma<1>, cudaFuncAttributeMaxDynamicSharedMemorySize, SMEM_GEMM);
    cudaFuncSetAttribute(gemm_mma<0>, cudaFuncAttributeMaxDynamicSharedMemorySize, SMEM_GEMM);

    // 1. in_proj GEMM (2-term fp16 split, ldmatrix, 2 CTAs/SM): split xs / z
    gemm_mma<1><<<dim3(NPROJ / 128, BL_ / 64), 128, SMEM_GEMM>>>(
        x, in_proj_w, nullptr, NPROJ, D_);

    // 2. x_proj GEMM with fused conv+silu (writes g_xsc), split-K partials
    gemm_xproj_fused<<<dim3(1, BL_ / 64, SPLITK), 256>>>(x_proj_w, conv_w, conv_b, ED_);

    // 3. fused reduce + prep_A + delta + SSM
    ssm_fused<<<(BL_ / 8) * 8, 256>>>(h, dt_proj_w, dt_proj_b, Dvec, A_log, hout);

    // 4. out_proj GEMM (2-term fp16 split, ldmatrix, 2 CTAs/SM)
    gemm_mma<0><<<dim3(D_ / 128, BL_ / 64), 128, SMEM_GEMM>>>(
        p_y, out_proj_w, out, D_, ED_);
}